// round 1
// baseline (speedup 1.0000x reference)
#include <cuda_runtime.h>
#include <math.h>

// ---------------------------------------------------------------------------
// Problem constants
// ---------------------------------------------------------------------------
#define BB   2
#define CC   64
#define HH   256
#define WW   256
#define KK9  9
#define DG   8
#define CG   8          // CC/DG
#define NOFF 144        // 2*KK*DG
#define NMSK 72         // KK*DG
#define NOM  216        // NOFF+NMSK
#define HW   65536      // HH*WW

// packed fp32x2 helpers (sm_100+)
#define FMA2(d,a,b,c) asm("fma.rn.f32x2 %0, %1, %2, %3;" : "=l"(d) : "l"(a), "l"(b), "l"(c))
#define PACK2(d,lo,hi) asm("mov.b64 %0, {%1, %2};" : "=l"(d) : "r"(__float_as_uint(lo)), "r"(__float_as_uint(hi)))

static __device__ __forceinline__ float lo32(unsigned long long v){ return __uint_as_float((unsigned)v); }
static __device__ __forceinline__ float hi32(unsigned long long v){ return __uint_as_float((unsigned)(v >> 32)); }

// scratch: [b][ch 0..215][h][w]; ch 0..143 = offset, 144..215 = sigmoid(mask)
__device__ float g_offmask[(size_t)BB * NOM * HW];

// ---------------------------------------------------------------------------
// Kernel 1: fused 3x3 conv over concat(ref, neighbour) -> 216 channels.
// Block: 16x16 output tile, 72 output channels. 288 threads (9 warps).
// Warp w owns oc [w*8, w*8+8); lane owns 8 pixels (lane + 32*jj).
// f32x2 accumulators: acc[o][j] packs pixels (lane+64j, lane+64j+32).
// ---------------------------------------------------------------------------
__global__ __launch_bounds__(288, 1)
void conv_offmask_kernel(const float* __restrict__ ref,
                         const float* __restrict__ nbr,
                         const float* __restrict__ off_w,
                         const float* __restrict__ off_b,
                         const float* __restrict__ mask_w,
                         const float* __restrict__ mask_b)
{
    __shared__ float patch[8 * 324];      // 8 ci x 18 x 18
    __shared__ float wsm[8 * 9 * 72];     // [(ci*9+k)*72 + oc]

    const int b      = blockIdx.z;
    const int ocBase = blockIdx.y * 72;
    const int ty     = (blockIdx.x >> 4) << 4;
    const int tx     = (blockIdx.x & 15) << 4;
    const int tid    = threadIdx.x;
    const int wid    = tid >> 5;
    const int lane   = tid & 31;

    unsigned long long acc[8][4];
    #pragma unroll
    for (int o = 0; o < 8; o++)
        #pragma unroll
        for (int j = 0; j < 4; j++) acc[o][j] = 0ull;

    int off_s[8];
    #pragma unroll
    for (int jj = 0; jj < 8; jj++) {
        int p = lane + 32 * jj;
        off_s[jj] = (p >> 4) * 18 + (p & 15);
    }

    const int koff[9] = {0, 1, 2, 18, 19, 20, 36, 37, 38};

    for (int chunk = 0; chunk < 16; chunk++) {
        const int ci0 = chunk * 8;
        __syncthreads();
        // ---- load input patch (zero-padded) ----
        for (int i = tid; i < 8 * 324; i += 288) {
            int c  = i / 324;
            int e  = i - c * 324;
            int iy = e / 18;
            int ix = e - iy * 18;
            int gy = ty - 1 + iy;
            int gx = tx - 1 + ix;
            float v = 0.f;
            int cg = ci0 + c;
            if ((unsigned)gy < 256u && (unsigned)gx < 256u) {
                const float* src = (cg < 64) ? ref : nbr;
                int ch = cg & 63;
                v = src[((b * 64 + ch) << 16) + (gy << 8) + gx];
            }
            patch[i] = v;
        }
        // ---- load weight slice ----
        for (int i = tid; i < 5184; i += 288) {
            int o  = i % 72;
            int ck = i / 72;
            int c  = ck / 9;
            int k  = ck - c * 9;
            int ocg = ocBase + o;
            int cig = ci0 + c;
            float w;
            if (ocg < NOFF) w = off_w[(ocg * 128 + cig) * 9 + k];
            else            w = mask_w[((ocg - NOFF) * 128 + cig) * 9 + k];
            wsm[i] = w;
        }
        __syncthreads();
        // ---- compute ----
        #pragma unroll
        for (int c = 0; c < 8; c++) {
            const float* pc = patch + c * 324;
            #pragma unroll
            for (int k = 0; k < 9; k++) {
                const float* wr = wsm + (c * 9 + k) * 72 + wid * 8;
                const float4 wa = *(const float4*)(wr);
                const float4 wb = *(const float4*)(wr + 4);
                unsigned long long w2[8];
                PACK2(w2[0], wa.x, wa.x); PACK2(w2[1], wa.y, wa.y);
                PACK2(w2[2], wa.z, wa.z); PACK2(w2[3], wa.w, wa.w);
                PACK2(w2[4], wb.x, wb.x); PACK2(w2[5], wb.y, wb.y);
                PACK2(w2[6], wb.z, wb.z); PACK2(w2[7], wb.w, wb.w);
                float v[8];
                #pragma unroll
                for (int jj = 0; jj < 8; jj++) v[jj] = pc[off_s[jj] + koff[k]];
                unsigned long long v2[4];
                #pragma unroll
                for (int j = 0; j < 4; j++) PACK2(v2[j], v[2 * j], v[2 * j + 1]);
                #pragma unroll
                for (int o = 0; o < 8; o++) {
                    #pragma unroll
                    for (int j = 0; j < 4; j++)
                        FMA2(acc[o][j], v2[j], w2[o], acc[o][j]);
                }
            }
        }
    }

    // ---- epilogue: bias (+sigmoid for mask channels), store ----
    const int ocb = ocBase + wid * 8;
    #pragma unroll
    for (int o = 0; o < 8; o++) {
        int oc = ocb + o;
        float bi = (oc < NOFF) ? off_b[oc] : mask_b[oc - NOFF];
        bool sig = (oc >= NOFF);
        float* dst = g_offmask + ((size_t)b * NOM + oc) * HW;
        #pragma unroll
        for (int jj = 0; jj < 8; jj++) {
            unsigned long long a = acc[o][jj >> 1];
            float val = (jj & 1) ? hi32(a) : lo32(a);
            val += bi;
            if (sig) val = 1.f / (1.f + __expf(-val));
            int p = lane + 32 * jj;
            dst[((ty + (p >> 4)) << 8) + tx + (p & 15)] = val;
        }
    }
}

// ---------------------------------------------------------------------------
// Kernel 2: deformable bilinear sampling + mask + einsum + bias.
// Block: 8x16 pixel tile (128 px) x all 64 output channels. 256 threads.
// Loop over g in [0,8): phase A fills S[72ck][128px] = sampled*mask,
// phase B does acc[64oc][128px] += Wg[72][64]^T applied (f32x2 GEMM).
// Warp = fixed oc-octet (broadcast W loads), lane = pixel quad.
// ---------------------------------------------------------------------------
__global__ __launch_bounds__(256, 2)
void samp_einsum_kernel(const float* __restrict__ nbr,
                        const float* __restrict__ weight,
                        const float* __restrict__ bias,
                        float* __restrict__ out)
{
    extern __shared__ float sm[];
    float* S  = sm;              // 72 * 128
    float* Wg = sm + 72 * 128;   // 72 * 64

    const int b   = blockIdx.z;
    const int ty  = blockIdx.y << 3;
    const int tx  = blockIdx.x << 4;
    const int tid = threadIdx.x;
    const int pxg = tid & 31;    // pixel quad id (4 px each)
    const int ocq = tid >> 5;    // oc octet id (== warp id)

    unsigned long long acc[8][2];
    #pragma unroll
    for (int o = 0; o < 8; o++) { acc[o][0] = 0ull; acc[o][1] = 0ull; }

    const float* om = g_offmask + (size_t)b * NOM * HW;

    for (int g = 0; g < 8; g++) {
        __syncthreads();
        // ---- fill per-group weight slice Wg[(c*9+k)*64 + oc] ----
        for (int i = tid; i < 4608; i += 256) {
            int oc = i & 63;
            int ck = i >> 6;
            int c  = ck / 9;
            int k  = ck - c * 9;
            Wg[i] = weight[(oc * 64 + g * 8 + c) * 9 + k];
        }
        // ---- sampling: 128 px * 9 k tasks ----
        for (int i = tid; i < 1152; i += 256) {
            int px = i & 127;
            int k  = i >> 7;
            int pr = px >> 4, pc = px & 15;
            int y = ty + pr, x = tx + pc;
            int pix = (y << 8) + x;
            int ch  = g * 9 + k;
            float dy = om[(ch * 2) * HW + pix];
            float dx = om[(ch * 2 + 1) * HW + pix];
            float m  = om[(NOFF + ch) * HW + pix];
            float sy = (float)(y - 1 + k / 3) + dy;
            float sx = (float)(x - 1 + (k - (k / 3) * 3)) + dx;
            float y0f = floorf(sy), x0f = floorf(sx);
            float wy = sy - y0f, wx = sx - x0f;
            int iy0 = (int)y0f, ix0 = (int)x0f;
            int iy1 = iy0 + 1, ix1 = ix0 + 1;
            bool vy0 = (unsigned)iy0 < 256u, vy1 = (unsigned)iy1 < 256u;
            bool vx0 = (unsigned)ix0 < 256u, vx1 = (unsigned)ix1 < 256u;
            float w00 = (1.f - wy) * (1.f - wx) * m;
            float w01 = (1.f - wy) * wx * m;
            float w10 = wy * (1.f - wx) * m;
            float w11 = wy * wx * m;
            bool v00 = vy0 && vx0, v01 = vy0 && vx1, v10 = vy1 && vx0, v11 = vy1 && vx1;
            int o00 = (iy0 << 8) + ix0;
            int o01 = o00 + 1;
            int o10 = o00 + 256;
            int o11 = o10 + 1;
            const float* base = nbr + ((b * 64 + g * 8) << 16);
            #pragma unroll
            for (int c = 0; c < 8; c++) {
                const float* pB = base + (c << 16);
                float v = 0.f;
                if (v00) v += w00 * pB[o00];
                if (v01) v += w01 * pB[o01];
                if (v10) v += w10 * pB[o10];
                if (v11) v += w11 * pB[o11];
                S[(c * 9 + k) * 128 + px] = v;
            }
        }
        __syncthreads();
        // ---- GEMM phase: acc[8oc][4px] += sum_ck W * S ----
        #pragma unroll 4
        for (int ck = 0; ck < 72; ck++) {
            const float4 s4 = *(const float4*)&S[ck * 128 + pxg * 4];
            unsigned long long s2a, s2b;
            PACK2(s2a, s4.x, s4.y);
            PACK2(s2b, s4.z, s4.w);
            const float* wr = Wg + ck * 64 + ocq * 8;
            const float4 wa = *(const float4*)(wr);
            const float4 wb = *(const float4*)(wr + 4);
            unsigned long long w2[8];
            PACK2(w2[0], wa.x, wa.x); PACK2(w2[1], wa.y, wa.y);
            PACK2(w2[2], wa.z, wa.z); PACK2(w2[3], wa.w, wa.w);
            PACK2(w2[4], wb.x, wb.x); PACK2(w2[5], wb.y, wb.y);
            PACK2(w2[6], wb.z, wb.z); PACK2(w2[7], wb.w, wb.w);
            #pragma unroll
            for (int o = 0; o < 8; o++) {
                FMA2(acc[o][0], s2a, w2[o], acc[o][0]);
                FMA2(acc[o][1], s2b, w2[o], acc[o][1]);
            }
        }
    }

    // ---- epilogue ----
    const int pr  = pxg >> 2;
    const int pc0 = (pxg & 3) << 2;
    #pragma unroll
    for (int o = 0; o < 8; o++) {
        int oc = ocq * 8 + o;
        float bi = bias[oc];
        float4 r;
        r.x = lo32(acc[o][0]) + bi;
        r.y = hi32(acc[o][0]) + bi;
        r.z = lo32(acc[o][1]) + bi;
        r.w = hi32(acc[o][1]) + bi;
        float* dst = out + ((b * 64 + oc) << 16) + ((ty + pr) << 8) + tx + pc0;
        *(float4*)dst = r;
    }
}

// ---------------------------------------------------------------------------
// Launch
// ---------------------------------------------------------------------------
extern "C" void kernel_launch(void* const* d_in, const int* in_sizes, int n_in,
                              void* d_out, int out_size)
{
    const float* ref    = (const float*)d_in[0];
    const float* nbr    = (const float*)d_in[1];
    const float* off_w  = (const float*)d_in[2];
    const float* off_b  = (const float*)d_in[3];
    const float* mask_w = (const float*)d_in[4];
    const float* mask_b = (const float*)d_in[5];
    const float* weight = (const float*)d_in[6];
    const float* bias   = (const float*)d_in[7];
    float* out = (float*)d_out;

    // Stage 1: conv -> offsets + sigmoid(mask)
    {
        dim3 grid(256, 3, BB);
        conv_offmask_kernel<<<grid, 288>>>(ref, nbr, off_w, off_b, mask_w, mask_b);
    }
    // Stage 2: sampling + einsum + bias
    {
        static int smem_set = 0;
        (void)smem_set;
        cudaFuncSetAttribute(samp_einsum_kernel,
                             cudaFuncAttributeMaxDynamicSharedMemorySize, 55296);
        dim3 grid(WW / 16, HH / 8, BB);
        samp_einsum_kernel<<<grid, 256, 55296>>>(nbr, weight, bias, out);
    }
}

// round 3
// speedup vs baseline: 2.4002x; 2.4002x over previous
#include <cuda_runtime.h>
#include <cuda_fp16.h>
#include <math.h>
#include <stdint.h>

// ---------------------------------------------------------------------------
// Problem constants
// ---------------------------------------------------------------------------
#define BB   2
#define CC   64
#define HH   256
#define WW   256
#define DG   8
#define CG   8
#define NOFF 144        // 2*9*DG
#define NMSK 72         // 9*DG
#define NOM  216
#define HW   65536

// packed fp32x2 helpers (sm_100+) for the sampling/einsum kernel
#define FMA2(d,a,b,c) asm("fma.rn.f32x2 %0, %1, %2, %3;" : "=l"(d) : "l"(a), "l"(b), "l"(c))
#define PACK2(d,lo,hi) asm("mov.b64 %0, {%1, %2};" : "=l"(d) : "r"(__float_as_uint(lo)), "r"(__float_as_uint(hi)))
static __device__ __forceinline__ float lo32(unsigned long long v){ return __uint_as_float((unsigned)v); }
static __device__ __forceinline__ float hi32(unsigned long long v){ return __uint_as_float((unsigned)(v >> 32)); }

// scratch: [b][ch 0..215][h][w]; ch 0..143 = offset, 144..215 = sigmoid(mask)
__device__ float g_offmask[(size_t)BB * NOM * HW];
// prepacked fp16 conv weights: [chunk 8][tap 9][oc 224][ci 16] halves
// = 258048 halves = 516096 B = 32256 uint4
__device__ uint4 g_wconv[32256];

// warp-level HMMA: D(16x8 f32) += A(16x16 f16, row) * B(16x8 f16, col)
#define MMA16816(d0,d1,d2,d3,a0,a1,a2,a3,b0,b1) \
    asm volatile("mma.sync.aligned.m16n8k16.row.col.f32.f16.f16.f32 " \
        "{%0,%1,%2,%3}, {%4,%5,%6,%7}, {%8,%9}, {%0,%1,%2,%3};" \
        : "+f"(d0), "+f"(d1), "+f"(d2), "+f"(d3) \
        : "r"(a0), "r"(a1), "r"(a2), "r"(a3), "r"(b0), "r"(b1))

// ---------------------------------------------------------------------------
// Kernel 0: prepack conv weights to fp16, chunk-major, ready-to-copy layout.
// idx -> ci_lo (16), oc (224), tap (9), chunk (8); ci = chunk*16 + ci_lo
// ---------------------------------------------------------------------------
__global__ void prepack_w_kernel(const float* __restrict__ off_w,
                                 const float* __restrict__ mask_w)
{
    int idx = blockIdx.x * 256 + threadIdx.x;
    if (idx >= 8 * 9 * 224 * 16) return;
    int cl = idx & 15;
    int r  = idx >> 4;
    int oc = r % 224;
    int r2 = r / 224;
    int t  = r2 % 9;
    int c  = r2 / 9;
    int ci = c * 16 + cl;
    float v = 0.f;
    if (oc < NOFF)      v = off_w[(oc * 128 + ci) * 9 + t];
    else if (oc < NOM)  v = mask_w[((oc - NOFF) * 128 + ci) * 9 + t];
    ((__half*)g_wconv)[idx] = __float2half_rn(v);
}

// ---------------------------------------------------------------------------
// Kernel 1: 3x3 conv as 9 shifted 1x1 HMMA GEMMs.
// Block: 8x16 px tile x 224 oc. 256 threads = 8 warps.
// Warp grid: wm = wid&1 (64 px), wn = wid>>1 (56 oc).
// smem: patch [18 py][18 px][16 ci] f16, 36 B/pixel-row (4B pad);
//       B slice [tap][oc 224][ci 16] f16 (32 B rows, conflict-free).
// ---------------------------------------------------------------------------
#define PATCH_OFF 0
#define PATCH_BYTES (324 * 36)            // 11664
#define WB_OFF    11712
#define WB_BYTES  (9 * 224 * 32)          // 64512
#define BIAS_OFF  (WB_OFF + WB_BYTES)     // 76224
#define SMEM_TOT  (BIAS_OFF + 224 * 4)    // 77120

__global__ __launch_bounds__(256, 1)
void conv_mma_kernel(const float* __restrict__ ref,
                     const float* __restrict__ nbr,
                     const float* __restrict__ off_b,
                     const float* __restrict__ mask_b)
{
    extern __shared__ char smem[];
    const int tid  = threadIdx.x;
    const int wid  = tid >> 5;
    const int lane = tid & 31;
    const int b  = blockIdx.z;
    const int ty = blockIdx.y << 3;
    const int tx = blockIdx.x << 4;
    const int wm = wid & 1;
    const int wn = wid >> 1;

    float* bias_s = (float*)(smem + BIAS_OFF);
    if (tid < 224) {
        float bi = 0.f;
        if (tid < NOFF)     bi = off_b[tid];
        else if (tid < NOM) bi = mask_b[tid - NOFF];
        bias_s[tid] = bi;
    }

    const float* ref_b = ref + ((size_t)b << 22);
    const float* nbr_b = nbr + ((size_t)b << 22);

    float acc[4][7][4];
    #pragma unroll
    for (int mt = 0; mt < 4; mt++)
        #pragma unroll
        for (int nt = 0; nt < 7; nt++)
            #pragma unroll
            for (int q = 0; q < 4; q++) acc[mt][nt][q] = 0.f;

    const int i4 = lane >> 2;          // 0..7
    const int k4 = lane & 3;           // 0..3

    for (int c = 0; c < 8; c++) {
        __syncthreads();
        // ---- load patch: 324 pixels x 8 ci-pairs ----
        #pragma unroll 1
        for (int i = tid; i < 2592; i += 256) {
            int px_lin = i % 324;
            int j      = i / 324;           // ci pair
            int py  = px_lin / 18;
            int pxx = px_lin - py * 18;
            int gy = ty - 1 + py;
            int gx = tx - 1 + pxx;
            int ci0 = c * 16 + 2 * j;
            float v0 = 0.f, v1 = 0.f;
            if ((unsigned)gy < 256u && (unsigned)gx < 256u) {
                const float* p = ((ci0 < 64) ? (ref_b + ((size_t)ci0 << 16))
                                             : (nbr_b + ((size_t)(ci0 - 64) << 16)))
                                 + (gy << 8) + gx;
                v0 = __ldg(p);
                v1 = __ldg(p + HW);
            }
            *(__half2*)(smem + PATCH_OFF + px_lin * 36 + j * 4) = __floats2half2_rn(v0, v1);
        }
        // ---- copy weight slice (prepacked, contiguous) ----
        {
            const uint4* src = g_wconv + c * 4032;
            uint4* dst = (uint4*)(smem + WB_OFF);
            #pragma unroll 1
            for (int i = tid; i < 4032; i += 256) dst[i] = __ldg(src + i);
        }
        __syncthreads();
        // ---- compute: 9 taps ----
        #pragma unroll 1
        for (int t = 0; t < 9; t++) {
            const int dy = t / 3;
            const int dx = t - dy * 3;
            // A fragments: 4 m-tiles (image rows wm*4+mt), cols 0..15 (+dx)
            uint32_t A[4][4];
            #pragma unroll
            for (int mt = 0; mt < 4; mt++) {
                int py = wm * 4 + mt + dy;
                const char* base = smem + PATCH_OFF + (py * 18 + dx) * 36;
                const char* a0p = base + i4 * 36 + k4 * 4;
                A[mt][0] = *(const uint32_t*)(a0p);
                A[mt][1] = *(const uint32_t*)(a0p + 288);       // cols +8
                A[mt][2] = *(const uint32_t*)(a0p + 16);        // ci +8
                A[mt][3] = *(const uint32_t*)(a0p + 288 + 16);
            }
            const char* bbase = smem + WB_OFF + t * 7168 + (wn * 56) * 32 + i4 * 32 + k4 * 4;
            #pragma unroll
            for (int nt = 0; nt < 7; nt++) {
                uint32_t b0 = *(const uint32_t*)(bbase + nt * 256);
                uint32_t b1 = *(const uint32_t*)(bbase + nt * 256 + 16);
                #pragma unroll
                for (int mt = 0; mt < 4; mt++) {
                    MMA16816(acc[mt][nt][0], acc[mt][nt][1], acc[mt][nt][2], acc[mt][nt][3],
                             A[mt][0], A[mt][1], A[mt][2], A[mt][3], b0, b1);
                }
            }
        }
    }

    // ---- epilogue: bias (+sigmoid for mask channels), store to g_offmask ----
    __syncthreads();
    float* omb = g_offmask + (size_t)b * NOM * HW;
    #pragma unroll
    for (int mt = 0; mt < 4; mt++) {
        int y = ty + wm * 4 + mt;
        #pragma unroll
        for (int nt = 0; nt < 7; nt++) {
            int oc0 = wn * 56 + nt * 8 + (lane & 3) * 2;
            if (oc0 >= NOM) continue;
            int c0 = lane >> 2;
            #pragma unroll
            for (int q = 0; q < 4; q++) {
                int oc = oc0 + (q & 1);
                if (oc >= NOM) continue;
                int col = c0 + ((q >> 1) << 3);
                float val = acc[mt][nt][q] + bias_s[oc];
                if (oc >= NOFF) val = 1.f / (1.f + __expf(-val));
                omb[(size_t)oc * HW + (y << 8) + tx + col] = val;
            }
        }
    }
}

// ---------------------------------------------------------------------------
// Kernel 2: deformable bilinear sampling + mask + einsum + bias.
// ---------------------------------------------------------------------------
__global__ __launch_bounds__(256, 2)
void samp_einsum_kernel(const float* __restrict__ nbr,
                        const float* __restrict__ weight,
                        const float* __restrict__ bias,
                        float* __restrict__ out)
{
    extern __shared__ float sm[];
    float* S  = sm;              // 72 * 128
    float* Wg = sm + 72 * 128;   // 72 * 64

    const int b   = blockIdx.z;
    const int ty  = blockIdx.y << 3;
    const int tx  = blockIdx.x << 4;
    const int tid = threadIdx.x;
    const int pxg = tid & 31;
    const int ocq = tid >> 5;

    unsigned long long acc[8][2];
    #pragma unroll
    for (int o = 0; o < 8; o++) { acc[o][0] = 0ull; acc[o][1] = 0ull; }

    const float* om = g_offmask + (size_t)b * NOM * HW;

    for (int g = 0; g < 8; g++) {
        __syncthreads();
        for (int i = tid; i < 4608; i += 256) {
            int oc = i & 63;
            int ck = i >> 6;
            int c  = ck / 9;
            int k  = ck - c * 9;
            Wg[i] = weight[(oc * 64 + g * 8 + c) * 9 + k];
        }
        for (int i = tid; i < 1152; i += 256) {
            int px = i & 127;
            int k  = i >> 7;
            int pr = px >> 4, pc = px & 15;
            int y = ty + pr, x = tx + pc;
            int pix = (y << 8) + x;
            int ch  = g * 9 + k;
            float dy = om[(ch * 2) * HW + pix];
            float dx = om[(ch * 2 + 1) * HW + pix];
            float m  = om[(NOFF + ch) * HW + pix];
            float sy = (float)(y - 1 + k / 3) + dy;
            float sx = (float)(x - 1 + (k - (k / 3) * 3)) + dx;
            float y0f = floorf(sy), x0f = floorf(sx);
            float wy = sy - y0f, wx = sx - x0f;
            int iy0 = (int)y0f, ix0 = (int)x0f;
            int iy1 = iy0 + 1, ix1 = ix0 + 1;
            bool vy0 = (unsigned)iy0 < 256u, vy1 = (unsigned)iy1 < 256u;
            bool vx0 = (unsigned)ix0 < 256u, vx1 = (unsigned)ix1 < 256u;
            float w00 = (1.f - wy) * (1.f - wx) * m;
            float w01 = (1.f - wy) * wx * m;
            float w10 = wy * (1.f - wx) * m;
            float w11 = wy * wx * m;
            bool v00 = vy0 && vx0, v01 = vy0 && vx1, v10 = vy1 && vx0, v11 = vy1 && vx1;
            int o00 = (iy0 << 8) + ix0;
            int o01 = o00 + 1;
            int o10 = o00 + 256;
            int o11 = o10 + 1;
            const float* base = nbr + ((b * 64 + g * 8) << 16);
            #pragma unroll
            for (int c = 0; c < 8; c++) {
                const float* pB = base + (c << 16);
                float v = 0.f;
                if (v00) v += w00 * pB[o00];
                if (v01) v += w01 * pB[o01];
                if (v10) v += w10 * pB[o10];
                if (v11) v += w11 * pB[o11];
                S[(c * 9 + k) * 128 + px] = v;
            }
        }
        __syncthreads();
        #pragma unroll 4
        for (int ck = 0; ck < 72; ck++) {
            const float4 s4 = *(const float4*)&S[ck * 128 + pxg * 4];
            unsigned long long s2a, s2b;
            PACK2(s2a, s4.x, s4.y);
            PACK2(s2b, s4.z, s4.w);
            const float* wr = Wg + ck * 64 + ocq * 8;
            const float4 wa = *(const float4*)(wr);
            const float4 wb = *(const float4*)(wr + 4);
            unsigned long long w2[8];
            PACK2(w2[0], wa.x, wa.x); PACK2(w2[1], wa.y, wa.y);
            PACK2(w2[2], wa.z, wa.z); PACK2(w2[3], wa.w, wa.w);
            PACK2(w2[4], wb.x, wb.x); PACK2(w2[5], wb.y, wb.y);
            PACK2(w2[6], wb.z, wb.z); PACK2(w2[7], wb.w, wb.w);
            #pragma unroll
            for (int o = 0; o < 8; o++) {
                FMA2(acc[o][0], s2a, w2[o], acc[o][0]);
                FMA2(acc[o][1], s2b, w2[o], acc[o][1]);
            }
        }
    }

    const int pr  = pxg >> 2;
    const int pc0 = (pxg & 3) << 2;
    #pragma unroll
    for (int o = 0; o < 8; o++) {
        int oc = ocq * 8 + o;
        float bi = bias[oc];
        float4 r;
        r.x = lo32(acc[o][0]) + bi;
        r.y = hi32(acc[o][0]) + bi;
        r.z = lo32(acc[o][1]) + bi;
        r.w = hi32(acc[o][1]) + bi;
        float* dst = out + ((b * 64 + oc) << 16) + ((ty + pr) << 8) + tx + pc0;
        *(float4*)dst = r;
    }
}

// ---------------------------------------------------------------------------
// Launch
// ---------------------------------------------------------------------------
extern "C" void kernel_launch(void* const* d_in, const int* in_sizes, int n_in,
                              void* d_out, int out_size)
{
    const float* ref    = (const float*)d_in[0];
    const float* nbr    = (const float*)d_in[1];
    const float* off_w  = (const float*)d_in[2];
    const float* off_b  = (const float*)d_in[3];
    const float* mask_w = (const float*)d_in[4];
    const float* mask_b = (const float*)d_in[5];
    const float* weight = (const float*)d_in[6];
    const float* bias   = (const float*)d_in[7];
    float* out = (float*)d_out;

    // Stage 0: prepack fp16 conv weights
    prepack_w_kernel<<<(8 * 9 * 224 * 16 + 255) / 256, 256>>>(off_w, mask_w);

    // Stage 1: conv -> offsets + sigmoid(mask), HMMA tensor path
    {
        cudaFuncSetAttribute(conv_mma_kernel,
                             cudaFuncAttributeMaxDynamicSharedMemorySize, SMEM_TOT);
        dim3 grid(WW / 16, HH / 8, BB);
        conv_mma_kernel<<<grid, 256, SMEM_TOT>>>(ref, nbr, off_b, mask_b);
    }
    // Stage 2: sampling + einsum + bias
    {
        cudaFuncSetAttribute(samp_einsum_kernel,
                             cudaFuncAttributeMaxDynamicSharedMemorySize, 55296);
        dim3 grid(WW / 16, HH / 8, BB);
        samp_einsum_kernel<<<grid, 256, 55296>>>(nbr, weight, bias, out);
    }
}

// round 4
// speedup vs baseline: 3.2121x; 1.3383x over previous
#include <cuda_runtime.h>
#include <cuda_fp16.h>
#include <math.h>
#include <stdint.h>

// ---------------------------------------------------------------------------
// Problem constants
// ---------------------------------------------------------------------------
#define BB   2
#define CC   64
#define HH   256
#define WW   256
#define DG   8
#define CG   8
#define NOFF 144        // 2*9*DG
#define NMSK 72         // 9*DG
#define NOM  216
#define HW   65536

// packed fp32x2 helpers (sm_100+)
#define FMA2(d,a,b,c) asm("fma.rn.f32x2 %0, %1, %2, %3;" : "=l"(d) : "l"(a), "l"(b), "l"(c))
#define PACK2(d,lo,hi) asm("mov.b64 %0, {%1, %2};" : "=l"(d) : "r"(__float_as_uint(lo)), "r"(__float_as_uint(hi)))
static __device__ __forceinline__ float lo32(unsigned long long v){ return __uint_as_float((unsigned)v); }
static __device__ __forceinline__ float hi32(unsigned long long v){ return __uint_as_float((unsigned)(v >> 32)); }

// scratch
__device__ float g_offmask[(size_t)BB * NOM * HW];          // conv output
__device__ float g_featT[(size_t)BB * HW * 128];            // [b][y][x][c] c0-63=ref, c64-127=nbr
__device__ uint4 g_wconv[32256];                             // [chunk8][tap9][oc224][ci16] f16

// warp-level HMMA
#define MMA16816(d0,d1,d2,d3,a0,a1,a2,a3,b0,b1) \
    asm volatile("mma.sync.aligned.m16n8k16.row.col.f32.f16.f16.f32 " \
        "{%0,%1,%2,%3}, {%4,%5,%6,%7}, {%8,%9}, {%0,%1,%2,%3};" \
        : "+f"(d0), "+f"(d1), "+f"(d2), "+f"(d3) \
        : "r"(a0), "r"(a1), "r"(a2), "r"(a3), "r"(b0), "r"(b1))

#define LDMATRIX_X4(r0,r1,r2,r3,addr) \
    asm volatile("ldmatrix.sync.aligned.m8n8.x4.shared.b16 {%0,%1,%2,%3}, [%4];" \
        : "=r"(r0), "=r"(r1), "=r"(r2), "=r"(r3) : "r"(addr))

#define CP_ASYNC16(dst, src) \
    asm volatile("cp.async.cg.shared.global [%0], [%1], 16;" :: "r"(dst), "l"(src))
#define CP_COMMIT() asm volatile("cp.async.commit_group;" ::: "memory")
#define CP_WAIT_ALL() asm volatile("cp.async.wait_group 0;" ::: "memory")

static __device__ __forceinline__ uint32_t smem_u32(const void* p) {
    uint32_t a;
    asm("{ .reg .u64 t; cvta.to.shared.u64 t, %1; cvt.u32.u64 %0, t; }" : "=r"(a) : "l"(p));
    return a;
}

// ---------------------------------------------------------------------------
// Kernel T: transpose concat(ref, nbr) to channel-last [b][y][x][128]
// Block: 32 x-pixels of one row, all 128 channels. 256 threads.
// ---------------------------------------------------------------------------
__global__ __launch_bounds__(256, 4)
void transpose_kernel(const float* __restrict__ ref, const float* __restrict__ nbr)
{
    __shared__ float t[128][33];
    const int b  = blockIdx.z;
    const int y  = blockIdx.y;
    const int x0 = blockIdx.x << 5;
    const int tid = threadIdx.x;

    #pragma unroll
    for (int i = 0; i < 16; i++) {
        int idx = tid + (i << 8);
        int c = idx >> 5;
        int x = idx & 31;
        const float* src = (c < 64) ? ref : nbr;
        t[c][x] = __ldg(src + (((size_t)b * 64 + (c & 63)) << 16) + (y << 8) + x0 + x);
    }
    __syncthreads();
    float* dst = g_featT + (((size_t)b << 16) + (y << 8) + x0) * 128;
    #pragma unroll
    for (int i = 0; i < 16; i++) {
        int idx = tid + (i << 8);
        int x = idx >> 7;
        int c = idx & 127;
        dst[(size_t)x * 128 + c] = t[c][x];
    }
}

// ---------------------------------------------------------------------------
// Kernel 0: prepack conv weights to fp16: [chunk][tap][oc224][ci16]
// ---------------------------------------------------------------------------
__global__ void prepack_w_kernel(const float* __restrict__ off_w,
                                 const float* __restrict__ mask_w)
{
    int idx = blockIdx.x * 256 + threadIdx.x;
    if (idx >= 8 * 9 * 224 * 16) return;
    int cl = idx & 15;
    int r  = idx >> 4;
    int oc = r % 224;
    int r2 = r / 224;
    int t  = r2 % 9;
    int c  = r2 / 9;
    int ci = c * 16 + cl;
    float v = 0.f;
    if (oc < NOFF)      v = off_w[(oc * 128 + ci) * 9 + t];
    else if (oc < NOM)  v = mask_w[((oc - NOFF) * 128 + ci) * 9 + t];
    ((__half*)g_wconv)[idx] = __float2half_rn(v);
}

// ---------------------------------------------------------------------------
// Kernel 1: 3x3 conv as 9 shifted 1x1 HMMA GEMMs, cp.async pipelined.
// Block: 8x16 px tile x 224 oc. 256 threads = 8 warps (wm = wid&1, wn = wid>>1).
// patch: [10 py][18 px] rows of 16 ci f16, 48 B pixel stride, double-buffered.
// weights: [tap][oc224][ci16] f16, double-buffered via cp.async.
// ---------------------------------------------------------------------------
#define PATCH_SZ  8704            // 180*48 rounded
#define WOFF      17408           // 2*PATCH_SZ
#define WSZ       64512           // 9*224*32
#define BIAS_OFF  146432          // WOFF + 2*WSZ
#define SMEM_TOT  147328

__global__ __launch_bounds__(256, 1)
void conv_mma_kernel(const float* __restrict__ off_b,
                     const float* __restrict__ mask_b)
{
    extern __shared__ char smem[];
    const uint32_t sb = smem_u32(smem);
    const int tid  = threadIdx.x;
    const int wid  = tid >> 5;
    const int lane = tid & 31;
    const int b  = blockIdx.z;
    const int ty = blockIdx.y << 3;
    const int tx = blockIdx.x << 4;
    const int wm = wid & 1;
    const int wn = wid >> 1;

    float* bias_s = (float*)(smem + BIAS_OFF);
    if (tid < 224) {
        float bi = 0.f;
        if (tid < NOFF)     bi = off_b[tid];
        else if (tid < NOM) bi = mask_b[tid - NOFF];
        bias_s[tid] = bi;
    }

    const float* ftb = g_featT + ((size_t)b << 16) * 128;

    // patch task -> (px_lin 0..179, half 0..1); precompute gmem validity/addr parts
    // task0 = tid, task1 = tid + 256 (valid if tid < 104)
    int pl0 = tid % 180, h0 = tid / 180;
    int t1v = (tid < 104);
    int pl1 = (tid + 256) % 180, h1 = (tid + 256) / 180;
    int py0 = pl0 / 18, px0 = pl0 - py0 * 18;
    int py1 = pl1 / 18, px1 = pl1 - py1 * 18;
    int gy0 = ty - 1 + py0, gx0 = tx - 1 + px0;
    int gy1 = ty - 1 + py1, gx1 = tx - 1 + px1;
    bool v0 = ((unsigned)gy0 < 256u) && ((unsigned)gx0 < 256u);
    bool v1 = t1v && ((unsigned)gy1 < 256u) && ((unsigned)gx1 < 256u);
    const float* base0 = ftb + ((size_t)((gy0 << 8) + gx0)) * 128 + h0 * 8;
    const float* base1 = ftb + ((size_t)((gy1 << 8) + gx1)) * 128 + h1 * 8;
    const uint32_t sts0 = (uint32_t)(pl0 * 48 + h0 * 16);
    const uint32_t sts1 = (uint32_t)(pl1 * 48 + h1 * 16);

    float acc[4][7][4];
    #pragma unroll
    for (int mt = 0; mt < 4; mt++)
        #pragma unroll
        for (int nt = 0; nt < 7; nt++)
            #pragma unroll
            for (int q = 0; q < 4; q++) acc[mt][nt][q] = 0.f;

    const int i4 = lane >> 2;
    const int k4 = lane & 3;
    const int lrow = lane & 15;
    const int lcol = lane >> 4;

    // ---- prologue: cp.async W(0), prefetch patch(0) ----
    float4 r0a, r0b, r1a, r1b;
    {
        const uint4* wsrc = g_wconv;
        uint32_t wdst = sb + WOFF;
        #pragma unroll
        for (int i = 0; i < 16; i++) {
            int idx = tid + (i << 8);
            if (idx < 4032) CP_ASYNC16(wdst + idx * 16, (const void*)(wsrc + idx));
        }
        CP_COMMIT();
        r0a = v0 ? __ldg((const float4*)base0) : make_float4(0,0,0,0);
        r0b = v0 ? __ldg((const float4*)(base0 + 4)) : make_float4(0,0,0,0);
        r1a = v1 ? __ldg((const float4*)base1) : make_float4(0,0,0,0);
        r1b = v1 ? __ldg((const float4*)(base1 + 4)) : make_float4(0,0,0,0);
    }

    for (int c = 0; c < 8; c++) {
        const int s = c & 1;
        CP_WAIT_ALL();
        __syncthreads();
        // ---- store prefetched patch(c) into buf s ----
        {
            uint32_t pb = sb + s * PATCH_SZ;
            __half2 h2[4];
            h2[0] = __floats2half2_rn(r0a.x, r0a.y);
            h2[1] = __floats2half2_rn(r0a.z, r0a.w);
            h2[2] = __floats2half2_rn(r0b.x, r0b.y);
            h2[3] = __floats2half2_rn(r0b.z, r0b.w);
            *(uint4*)(smem + s * PATCH_SZ + sts0) = *(uint4*)h2;
            if (t1v) {
                h2[0] = __floats2half2_rn(r1a.x, r1a.y);
                h2[1] = __floats2half2_rn(r1a.z, r1a.w);
                h2[2] = __floats2half2_rn(r1b.x, r1b.y);
                h2[3] = __floats2half2_rn(r1b.z, r1b.w);
                *(uint4*)(smem + s * PATCH_SZ + sts1) = *(uint4*)h2;
            }
            (void)pb;
        }
        // ---- issue next chunk loads ----
        if (c < 7) {
            const uint4* wsrc = g_wconv + (c + 1) * 4032;
            uint32_t wdst = sb + WOFF + (s ^ 1) * WSZ;
            #pragma unroll
            for (int i = 0; i < 16; i++) {
                int idx = tid + (i << 8);
                if (idx < 4032) CP_ASYNC16(wdst + idx * 16, (const void*)(wsrc + idx));
            }
            CP_COMMIT();
            int cb = (c + 1) * 16;
            r0a = v0 ? __ldg((const float4*)(base0 + cb)) : make_float4(0,0,0,0);
            r0b = v0 ? __ldg((const float4*)(base0 + cb + 4)) : make_float4(0,0,0,0);
            r1a = v1 ? __ldg((const float4*)(base1 + cb)) : make_float4(0,0,0,0);
            r1b = v1 ? __ldg((const float4*)(base1 + cb + 4)) : make_float4(0,0,0,0);
        }
        __syncthreads();
        // ---- MMA chunk c ----
        const uint32_t patch_s = sb + s * PATCH_SZ;
        const uint32_t wbuf = sb + WOFF + s * WSZ;
        #pragma unroll 1
        for (int t = 0; t < 9; t++) {
            const int dy = t / 3;
            const int dx = t - dy * 3;
            uint32_t A[4][4];
            #pragma unroll
            for (int mt = 0; mt < 4; mt++) {
                int py = wm * 4 + mt + dy;
                uint32_t addr = patch_s + (uint32_t)((py * 18 + dx + lrow) * 48 + lcol * 16);
                LDMATRIX_X4(A[mt][0], A[mt][1], A[mt][2], A[mt][3], addr);
            }
            const uint32_t bbase = wbuf + (uint32_t)(t * 7168 + (wn * 56) * 32 + i4 * 32 + k4 * 4);
            #pragma unroll
            for (int nt = 0; nt < 7; nt++) {
                uint32_t b0, b1;
                asm volatile("ld.shared.b32 %0, [%1];" : "=r"(b0) : "r"(bbase + nt * 256));
                asm volatile("ld.shared.b32 %0, [%1];" : "=r"(b1) : "r"(bbase + nt * 256 + 16));
                #pragma unroll
                for (int mt = 0; mt < 4; mt++) {
                    MMA16816(acc[mt][nt][0], acc[mt][nt][1], acc[mt][nt][2], acc[mt][nt][3],
                             A[mt][0], A[mt][1], A[mt][2], A[mt][3], b0, b1);
                }
            }
        }
    }

    // ---- epilogue ----
    __syncthreads();
    float* omb = g_offmask + (size_t)b * NOM * HW;
    #pragma unroll
    for (int mt = 0; mt < 4; mt++) {
        int y = ty + wm * 4 + mt;
        #pragma unroll
        for (int nt = 0; nt < 7; nt++) {
            int oc0 = wn * 56 + nt * 8 + (lane & 3) * 2;
            if (oc0 >= NOM) continue;
            int c0 = lane >> 2;
            #pragma unroll
            for (int q = 0; q < 4; q++) {
                int oc = oc0 + (q & 1);
                if (oc >= NOM) continue;
                int col = c0 + ((q >> 1) << 3);
                float val = acc[mt][nt][q] + bias_s[oc];
                if (oc >= NOFF) val = 1.f / (1.f + __expf(-val));
                omb[(size_t)oc * HW + (y << 8) + tx + col] = val;
            }
        }
    }
}

// ---------------------------------------------------------------------------
// Kernel 2: deformable bilinear sampling (channel-last) + einsum + bias.
// ---------------------------------------------------------------------------
__global__ __launch_bounds__(256, 2)
void samp_einsum_kernel(const float* __restrict__ weight,
                        const float* __restrict__ bias,
                        float* __restrict__ out)
{
    extern __shared__ float sm[];
    float* S  = sm;              // 72 * 128
    float* Wg = sm + 72 * 128;   // 72 * 64

    const int b   = blockIdx.z;
    const int ty  = blockIdx.y << 3;
    const int tx  = blockIdx.x << 4;
    const int tid = threadIdx.x;
    const int pxg = tid & 31;
    const int ocq = tid >> 5;

    unsigned long long acc[8][2];
    #pragma unroll
    for (int o = 0; o < 8; o++) { acc[o][0] = 0ull; acc[o][1] = 0ull; }

    const float* om = g_offmask + (size_t)b * NOM * HW;
    const float* ftb = g_featT + ((size_t)b << 16) * 128;

    for (int g = 0; g < 8; g++) {
        __syncthreads();
        for (int i = tid; i < 4608; i += 256) {
            int oc = i & 63;
            int ck = i >> 6;
            int c  = ck / 9;
            int k  = ck - c * 9;
            Wg[i] = weight[(oc * 64 + g * 8 + c) * 9 + k];
        }
        const int cbase = 64 + g * 8;
        for (int i = tid; i < 1152; i += 256) {
            int px = i & 127;
            int k  = i >> 7;
            int pr = px >> 4, pc = px & 15;
            int y = ty + pr, x = tx + pc;
            int pix = (y << 8) + x;
            int ch  = g * 9 + k;
            float dy = om[(ch * 2) * HW + pix];
            float dx = om[(ch * 2 + 1) * HW + pix];
            float m  = om[(NOFF + ch) * HW + pix];
            float sy = (float)(y - 1 + k / 3) + dy;
            float sx = (float)(x - 1 + (k - (k / 3) * 3)) + dx;
            float y0f = floorf(sy), x0f = floorf(sx);
            float wy = sy - y0f, wx = sx - x0f;
            int iy0 = (int)y0f, ix0 = (int)x0f;
            int iy1 = iy0 + 1, ix1 = ix0 + 1;
            bool vy0 = (unsigned)iy0 < 256u, vy1 = (unsigned)iy1 < 256u;
            bool vx0 = (unsigned)ix0 < 256u, vx1 = (unsigned)ix1 < 256u;
            float w00 = (vy0 && vx0) ? (1.f - wy) * (1.f - wx) * m : 0.f;
            float w01 = (vy0 && vx1) ? (1.f - wy) * wx * m : 0.f;
            float w10 = (vy1 && vx0) ? wy * (1.f - wx) * m : 0.f;
            float w11 = (vy1 && vx1) ? wy * wx * m : 0.f;
            int y0c = min(max(iy0, 0), 255), y1c = min(max(iy1, 0), 255);
            int x0c = min(max(ix0, 0), 255), x1c = min(max(ix1, 0), 255);
            const float* p00 = ftb + ((size_t)((y0c << 8) + x0c) << 7) + cbase;
            const float* p01 = ftb + ((size_t)((y0c << 8) + x1c) << 7) + cbase;
            const float* p10 = ftb + ((size_t)((y1c << 8) + x0c) << 7) + cbase;
            const float* p11 = ftb + ((size_t)((y1c << 8) + x1c) << 7) + cbase;
            float t00[8], t01[8], t10[8], t11[8];
            *(float4*)(t00) = __ldg((const float4*)p00);
            *(float4*)(t00 + 4) = __ldg((const float4*)(p00 + 4));
            *(float4*)(t01) = __ldg((const float4*)p01);
            *(float4*)(t01 + 4) = __ldg((const float4*)(p01 + 4));
            *(float4*)(t10) = __ldg((const float4*)p10);
            *(float4*)(t10 + 4) = __ldg((const float4*)(p10 + 4));
            *(float4*)(t11) = __ldg((const float4*)p11);
            *(float4*)(t11 + 4) = __ldg((const float4*)(p11 + 4));
            #pragma unroll
            for (int c = 0; c < 8; c++) {
                float v = w00 * t00[c] + w01 * t01[c] + w10 * t10[c] + w11 * t11[c];
                S[(c * 9 + k) * 128 + px] = v;
            }
        }
        __syncthreads();
        #pragma unroll 4
        for (int ck = 0; ck < 72; ck++) {
            const float4 s4 = *(const float4*)&S[ck * 128 + pxg * 4];
            unsigned long long s2a, s2b;
            PACK2(s2a, s4.x, s4.y);
            PACK2(s2b, s4.z, s4.w);
            const float* wr = Wg + ck * 64 + ocq * 8;
            const float4 wa = *(const float4*)(wr);
            const float4 wb = *(const float4*)(wr + 4);
            unsigned long long w2[8];
            PACK2(w2[0], wa.x, wa.x); PACK2(w2[1], wa.y, wa.y);
            PACK2(w2[2], wa.z, wa.z); PACK2(w2[3], wa.w, wa.w);
            PACK2(w2[4], wb.x, wb.x); PACK2(w2[5], wb.y, wb.y);
            PACK2(w2[6], wb.z, wb.z); PACK2(w2[7], wb.w, wb.w);
            #pragma unroll
            for (int o = 0; o < 8; o++) {
                FMA2(acc[o][0], s2a, w2[o], acc[o][0]);
                FMA2(acc[o][1], s2b, w2[o], acc[o][1]);
            }
        }
    }

    const int pr  = pxg >> 2;
    const int pc0 = (pxg & 3) << 2;
    #pragma unroll
    for (int o = 0; o < 8; o++) {
        int oc = ocq * 8 + o;
        float bi = bias[oc];
        float4 r;
        r.x = lo32(acc[o][0]) + bi;
        r.y = hi32(acc[o][0]) + bi;
        r.z = lo32(acc[o][1]) + bi;
        r.w = hi32(acc[o][1]) + bi;
        float* dst = out + ((b * 64 + oc) << 16) + ((ty + pr) << 8) + tx + pc0;
        *(float4*)dst = r;
    }
}

// ---------------------------------------------------------------------------
// Launch
// ---------------------------------------------------------------------------
extern "C" void kernel_launch(void* const* d_in, const int* in_sizes, int n_in,
                              void* d_out, int out_size)
{
    const float* ref    = (const float*)d_in[0];
    const float* nbr    = (const float*)d_in[1];
    const float* off_w  = (const float*)d_in[2];
    const float* off_b  = (const float*)d_in[3];
    const float* mask_w = (const float*)d_in[4];
    const float* mask_b = (const float*)d_in[5];
    const float* weight = (const float*)d_in[6];
    const float* bias   = (const float*)d_in[7];
    float* out = (float*)d_out;

    // Stage T: channel-last transpose of concat(ref, nbr)
    {
        dim3 grid(WW / 32, HH, BB);
        transpose_kernel<<<grid, 256>>>(ref, nbr);
    }
    // Stage 0: prepack fp16 conv weights
    prepack_w_kernel<<<(8 * 9 * 224 * 16 + 255) / 256, 256>>>(off_w, mask_w);

    // Stage 1: conv -> offsets + sigmoid(mask), HMMA + cp.async pipeline
    {
        cudaFuncSetAttribute(conv_mma_kernel,
                             cudaFuncAttributeMaxDynamicSharedMemorySize, SMEM_TOT);
        dim3 grid(WW / 16, HH / 8, BB);
        conv_mma_kernel<<<grid, 256, SMEM_TOT>>>(off_b, mask_b);
    }
    // Stage 2: sampling + einsum + bias
    {
        cudaFuncSetAttribute(samp_einsum_kernel,
                             cudaFuncAttributeMaxDynamicSharedMemorySize, 55296);
        dim3 grid(WW / 16, HH / 8, BB);
        samp_einsum_kernel<<<grid, 256, 55296>>>(weight, bias, out);
    }
}

// round 5
// speedup vs baseline: 7.0869x; 2.2063x over previous
#include <cuda_runtime.h>
#include <cuda_fp16.h>
#include <math.h>
#include <stdint.h>

// ---------------------------------------------------------------------------
// Problem constants
// ---------------------------------------------------------------------------
#define BB   2
#define CC   64
#define HH   256
#define WW   256
#define DG   8
#define CG   8
#define NOFF 144
#define NMSK 72
#define NOM  216
#define HW   65536

// scratch
__device__ float  g_offmask[(size_t)BB * NOM * HW];   // conv output (fp32 planes)
__device__ __half g_featT[(size_t)BB * HW * 128];     // [b][y][x][128c] fp16, c0-63 ref, 64-127 nbr
__device__ uint4  g_wconv[32256];                     // conv W: [chunk8][tap9][oc224][ci16] f16
__device__ uint4  g_weinsum[5632];                    // einsum W: [g8][oc64][ck88] f16 (pad 72->88)

// warp-level HMMA
#define MMA16816(d0,d1,d2,d3,a0,a1,a2,a3,b0,b1) \
    asm volatile("mma.sync.aligned.m16n8k16.row.col.f32.f16.f16.f32 " \
        "{%0,%1,%2,%3}, {%4,%5,%6,%7}, {%8,%9}, {%0,%1,%2,%3};" \
        : "+f"(d0), "+f"(d1), "+f"(d2), "+f"(d3) \
        : "r"(a0), "r"(a1), "r"(a2), "r"(a3), "r"(b0), "r"(b1))

#define LDMATRIX_X4(r0,r1,r2,r3,addr) \
    asm volatile("ldmatrix.sync.aligned.m8n8.x4.shared.b16 {%0,%1,%2,%3}, [%4];" \
        : "=r"(r0), "=r"(r1), "=r"(r2), "=r"(r3) : "r"(addr))

#define CP_ASYNC16(dst, src) \
    asm volatile("cp.async.cg.shared.global [%0], [%1], 16;" :: "r"(dst), "l"(src))
#define CP_ASYNC16Z(dst, src, sz) \
    asm volatile("cp.async.cg.shared.global [%0], [%1], 16, %2;" :: "r"(dst), "l"(src), "r"(sz))
#define CP_COMMIT()  asm volatile("cp.async.commit_group;" ::: "memory")
#define CP_WAIT_ALL() asm volatile("cp.async.wait_group 0;" ::: "memory")
#define CP_WAIT_1()  asm volatile("cp.async.wait_group 1;" ::: "memory")

static __device__ __forceinline__ uint32_t smem_u32(const void* p) {
    uint32_t a;
    asm("{ .reg .u64 t; cvta.to.shared.u64 t, %1; cvt.u32.u64 %0, t; }" : "=r"(a) : "l"(p));
    return a;
}

// ---------------------------------------------------------------------------
// Kernel T: transpose concat(ref, nbr) to channel-last fp16 [b][y][x][128]
// ---------------------------------------------------------------------------
__global__ __launch_bounds__(256, 4)
void transpose_kernel(const float* __restrict__ ref, const float* __restrict__ nbr)
{
    __shared__ float t[128][33];
    const int b  = blockIdx.z;
    const int y  = blockIdx.y;
    const int x0 = blockIdx.x << 5;
    const int tid = threadIdx.x;

    #pragma unroll
    for (int i = 0; i < 16; i++) {
        int idx = tid + (i << 8);
        int c = idx >> 5;
        int x = idx & 31;
        const float* src = (c < 64) ? ref : nbr;
        t[c][x] = __ldg(src + (((size_t)b * 64 + (c & 63)) << 16) + (y << 8) + x0 + x);
    }
    __syncthreads();
    __half* dst = g_featT + ((((size_t)b << 16) + (y << 8) + x0) << 7);
    #pragma unroll
    for (int i = 0; i < 8; i++) {
        int idx = tid + (i << 8);      // 0..2047
        int x  = idx >> 6;
        int c2 = idx & 63;
        __half2 h = __floats2half2_rn(t[2 * c2][x], t[2 * c2 + 1][x]);
        *(__half2*)(dst + (size_t)x * 128 + 2 * c2) = h;
    }
}

// ---------------------------------------------------------------------------
// Kernel 0a: prepack conv weights fp16 [chunk][tap][oc224][ci16]
// ---------------------------------------------------------------------------
__global__ void prepack_w_kernel(const float* __restrict__ off_w,
                                 const float* __restrict__ mask_w)
{
    int idx = blockIdx.x * 256 + threadIdx.x;
    if (idx >= 8 * 9 * 224 * 16) return;
    int cl = idx & 15;
    int r  = idx >> 4;
    int oc = r % 224;
    int r2 = r / 224;
    int t  = r2 % 9;
    int c  = r2 / 9;
    int ci = c * 16 + cl;
    float v = 0.f;
    if (oc < NOFF)      v = off_w[(oc * 128 + ci) * 9 + t];
    else if (oc < NOM)  v = mask_w[((oc - NOFF) * 128 + ci) * 9 + t];
    ((__half*)g_wconv)[idx] = __float2half_rn(v);
}

// ---------------------------------------------------------------------------
// Kernel 0b: prepack einsum weights fp16 [g][oc 64][ck2 88], ck2 = k*8+c
// ---------------------------------------------------------------------------
__global__ void prepack_we_kernel(const float* __restrict__ weight)
{
    int idx = blockIdx.x * 256 + threadIdx.x;
    if (idx >= 8 * 64 * 88) return;
    int ck2 = idx % 88;
    int r   = idx / 88;
    int oc  = r & 63;
    int g   = r >> 6;
    float v = 0.f;
    if (ck2 < 72) {
        int k = ck2 >> 3;
        int c = ck2 & 7;
        v = weight[(oc * 64 + g * 8 + c) * 9 + k];
    }
    ((__half*)g_weinsum)[idx] = __float2half_rn(v);
}

// ---------------------------------------------------------------------------
// Kernel 1: 3x3 conv as 9 shifted 1x1 HMMA GEMMs, fully cp.async pipelined.
// ---------------------------------------------------------------------------
#define PATCH_SZ  8704
#define WOFF      17408
#define WSZ       64512
#define BIAS_OFF  146432
#define SMEM_TOT  147328

__global__ __launch_bounds__(256, 1)
void conv_mma_kernel(const float* __restrict__ off_b,
                     const float* __restrict__ mask_b)
{
    extern __shared__ char smem[];
    const uint32_t sb = smem_u32(smem);
    const int tid  = threadIdx.x;
    const int wid  = tid >> 5;
    const int lane = tid & 31;
    const int b  = blockIdx.z;
    const int ty = blockIdx.y << 3;
    const int tx = blockIdx.x << 4;
    const int wm = wid & 1;
    const int wn = wid >> 1;

    float* bias_s = (float*)(smem + BIAS_OFF);
    if (tid < 224) {
        float bi = 0.f;
        if (tid < NOFF)     bi = off_b[tid];
        else if (tid < NOM) bi = mask_b[tid - NOFF];
        bias_s[tid] = bi;
    }

    const __half* ftb = g_featT + (((size_t)b << 16) << 7);

    // patch tasks: (pl 0..179, h 0..1); task0 = tid, task1 = tid+256 (tid<104)
    int pl0 = tid % 180, h0 = tid / 180;
    int t1v = (tid < 104);
    int pl1 = (tid + 256) % 180, h1 = (tid + 256) / 180;
    int py0 = pl0 / 18, px0 = pl0 - py0 * 18;
    int py1 = pl1 / 18, px1 = pl1 - py1 * 18;
    int gy0 = ty - 1 + py0, gx0 = tx - 1 + px0;
    int gy1 = ty - 1 + py1, gx1 = tx - 1 + px1;
    bool v0 = ((unsigned)gy0 < 256u) && ((unsigned)gx0 < 256u);
    bool v1 = t1v && ((unsigned)gy1 < 256u) && ((unsigned)gx1 < 256u);
    const __half* src0 = ftb + (((size_t)(v0 ? ((gy0 << 8) + gx0) : 0)) << 7) + h0 * 8;
    const __half* src1 = ftb + (((size_t)(v1 ? ((gy1 << 8) + gx1) : 0)) << 7) + h1 * 8;
    const uint32_t d0 = (uint32_t)(pl0 * 48 + h0 * 16);
    const uint32_t d1 = (uint32_t)(pl1 * 48 + h1 * 16);
    const uint32_t z0 = v0 ? 16u : 0u;
    const uint32_t z1 = v1 ? 16u : 0u;

    float acc[4][7][4];
    #pragma unroll
    for (int mt = 0; mt < 4; mt++)
        #pragma unroll
        for (int nt = 0; nt < 7; nt++)
            #pragma unroll
            for (int q = 0; q < 4; q++) acc[mt][nt][q] = 0.f;

    const int i4 = lane >> 2;
    const int k4 = lane & 3;
    const int lrow = lane & 15;
    const int lcol = lane >> 4;

    // prologue: issue chunk 0 (weights + patch)
    {
        const uint4* wsrc = g_wconv;
        uint32_t wdst = sb + WOFF;
        #pragma unroll
        for (int i = 0; i < 16; i++) {
            int idx = tid + (i << 8);
            if (idx < 4032) CP_ASYNC16(wdst + idx * 16, (const void*)(wsrc + idx));
        }
        CP_ASYNC16Z(sb + d0, (const void*)src0, z0);
        if (t1v) CP_ASYNC16Z(sb + d1, (const void*)src1, z1);
        CP_COMMIT();
    }

    for (int c = 0; c < 8; c++) {
        const int s = c & 1;
        __syncthreads();   // all warps done with MMA(c-1) (buffer s^1) before refill
        if (c < 7) {
            const uint4* wsrc = g_wconv + (c + 1) * 4032;
            uint32_t wdst = sb + WOFF + (s ^ 1) * WSZ;
            #pragma unroll
            for (int i = 0; i < 16; i++) {
                int idx = tid + (i << 8);
                if (idx < 4032) CP_ASYNC16(wdst + idx * 16, (const void*)(wsrc + idx));
            }
            int cb = (c + 1) * 16;
            CP_ASYNC16Z(sb + (s ^ 1) * PATCH_SZ + d0, (const void*)(src0 + cb), z0);
            if (t1v) CP_ASYNC16Z(sb + (s ^ 1) * PATCH_SZ + d1, (const void*)(src1 + cb), z1);
            CP_COMMIT();
            CP_WAIT_1();
        } else {
            CP_WAIT_ALL();
        }
        __syncthreads();
        // ---- MMA chunk c ----
        const uint32_t patch_s = sb + s * PATCH_SZ;
        const uint32_t wbuf = sb + WOFF + s * WSZ;
        #pragma unroll 1
        for (int t = 0; t < 9; t++) {
            const int dy = t / 3;
            const int dx = t - dy * 3;
            uint32_t A[4][4];
            #pragma unroll
            for (int mt = 0; mt < 4; mt++) {
                int py = wm * 4 + mt + dy;
                uint32_t addr = patch_s + (uint32_t)((py * 18 + dx + lrow) * 48 + lcol * 16);
                LDMATRIX_X4(A[mt][0], A[mt][1], A[mt][2], A[mt][3], addr);
            }
            const uint32_t bbase = wbuf + (uint32_t)(t * 7168 + (wn * 56) * 32 + i4 * 32 + k4 * 4);
            #pragma unroll
            for (int nt = 0; nt < 7; nt++) {
                uint32_t b0, b1;
                asm volatile("ld.shared.b32 %0, [%1];" : "=r"(b0) : "r"(bbase + nt * 256));
                asm volatile("ld.shared.b32 %0, [%1];" : "=r"(b1) : "r"(bbase + nt * 256 + 16));
                #pragma unroll
                for (int mt = 0; mt < 4; mt++) {
                    MMA16816(acc[mt][nt][0], acc[mt][nt][1], acc[mt][nt][2], acc[mt][nt][3],
                             A[mt][0], A[mt][1], A[mt][2], A[mt][3], b0, b1);
                }
            }
        }
    }

    // ---- epilogue ----
    __syncthreads();
    float* omb = g_offmask + (size_t)b * NOM * HW;
    #pragma unroll
    for (int mt = 0; mt < 4; mt++) {
        int y = ty + wm * 4 + mt;
        #pragma unroll
        for (int nt = 0; nt < 7; nt++) {
            int oc0 = wn * 56 + nt * 8 + (lane & 3) * 2;
            if (oc0 >= NOM) continue;
            int c0 = lane >> 2;
            #pragma unroll
            for (int q = 0; q < 4; q++) {
                int oc = oc0 + (q & 1);
                if (oc >= NOM) continue;
                int col = c0 + ((q >> 1) << 3);
                float val = acc[mt][nt][q] + bias_s[oc];
                if (oc >= NOFF) val = 1.f / (1.f + __expf(-val));
                omb[(size_t)oc * HW + (y << 8) + tx + col] = val;
            }
        }
    }
}

// ---------------------------------------------------------------------------
// Kernel 2: deformable sampling from smem halo tile + HMMA einsum.
// Block: 8x16 px tile (128 px) x 64 oc. 256 threads = 8 warps.
// smem: S[128 px][88 ck] f16 (stride 176B), tile 20x28 px x 8ch f16 (16B/px),
//       Wh[64 oc][88 ck] f16.
// ---------------------------------------------------------------------------
#define S_OFF     0
#define S_BYTES   22528       // 128*176
#define TILE_OFF  22528
#define TILE_BYTES 8960       // 560*16
#define WH_OFF    31488
#define WH_BYTES  11264       // 64*176
#define SMEM_SAMP 42752

__global__ __launch_bounds__(256, 2)
void samp_einsum_kernel(const float* __restrict__ bias,
                        float* __restrict__ out)
{
    extern __shared__ char smem[];
    const uint32_t sb = smem_u32(smem);
    const int b   = blockIdx.z;
    const int ty  = blockIdx.y << 3;
    const int tx  = blockIdx.x << 4;
    const int tid = threadIdx.x;
    const int wid  = tid >> 5;
    const int lane = tid & 31;
    const int wm = wid & 3;      // px group (32 each)
    const int wn = wid >> 2;     // oc group (32 each)
    const int i4 = lane >> 2;
    const int k4 = lane & 3;
    const int lrow = lane & 15;
    const int lcol = lane >> 4;

    const float*  om  = g_offmask + (size_t)b * NOM * HW;
    const __half* ftb = g_featT + (((size_t)b << 16) << 7);

    // zero K-pad region of S (halves 72..87 per px row) once
    if (tid < 128) {
        uint4 z = make_uint4(0, 0, 0, 0);
        *(uint4*)(smem + S_OFF + tid * 176 + 144) = z;
        *(uint4*)(smem + S_OFF + tid * 176 + 160) = z;
    }

    float acc[2][4][4];
    #pragma unroll
    for (int mt = 0; mt < 2; mt++)
        #pragma unroll
        for (int nt = 0; nt < 4; nt++)
            #pragma unroll
            for (int q = 0; q < 4; q++) acc[mt][nt][q] = 0.f;

    for (int g = 0; g < 8; g++) {
        const int cbase = 64 + g * 8;
        __syncthreads();    // GEMM(g-1)/tile reads done before refill
        // ---- issue tile + Wh cp.async ----
        #pragma unroll
        for (int jj = 0; jj < 3; jj++) {
            int j = tid + jj * 256;
            if (j < 560) {
                int r  = j / 28;
                int cc = j - r * 28;
                int gy = ty - 6 + r;
                int gx = tx - 6 + cc;
                bool pv = ((unsigned)gy < 256u) && ((unsigned)gx < 256u);
                const __half* src = ftb + (((size_t)(pv ? ((gy << 8) + gx) : 0)) << 7) + cbase;
                CP_ASYNC16Z(sb + TILE_OFF + j * 16, (const void*)src, pv ? 16u : 0u);
            }
        }
        #pragma unroll
        for (int jj = 0; jj < 3; jj++) {
            int j = tid + jj * 256;
            if (j < 704) CP_ASYNC16(sb + WH_OFF + j * 16, (const void*)(g_weinsum + g * 704 + j));
        }
        CP_COMMIT();

        // ---- stage 1: offsets -> indices/weights (overlaps cp.async) ----
        float tw0[5], tw1[5], tw2[5], tw3[5];
        int tiy[5], tix[5];
        #pragma unroll
        for (int t = 0; t < 5; t++) {
            int i = tid + t * 256;
            if (i < 1152) {
                int px = i & 127;
                int k  = i >> 7;
                int pr = px >> 4, pc = px & 15;
                int y = ty + pr, x = tx + pc;
                int pix = (y << 8) + x;
                int ch  = g * 9 + k;
                float dy = om[(ch * 2) * HW + pix];
                float dx = om[(ch * 2 + 1) * HW + pix];
                float m  = om[(NOFF + ch) * HW + pix];
                float sy = (float)(y - 1 + k / 3) + dy;
                float sx = (float)(x - 1 + (k - (k / 3) * 3)) + dx;
                float y0f = floorf(sy), x0f = floorf(sx);
                float wy = sy - y0f, wx = sx - x0f;
                tiy[t] = (int)y0f;
                tix[t] = (int)x0f;
                tw0[t] = (1.f - wy) * (1.f - wx) * m;
                tw1[t] = (1.f - wy) * wx * m;
                tw2[t] = wy * (1.f - wx) * m;
                tw3[t] = wy * wx * m;
            }
        }
        CP_WAIT_ALL();
        __syncthreads();

        // ---- stage 2: bilinear from smem tile, store S fp16 ----
        #pragma unroll
        for (int t = 0; t < 5; t++) {
            int i = tid + t * 256;
            if (i < 1152) {
                int px = i & 127;
                int k  = i >> 7;
                int ry = tiy[t] - (ty - 6);
                int rx = tix[t] - (tx - 6);
                float a8[8];
                #pragma unroll
                for (int cc = 0; cc < 8; cc++) a8[cc] = 0.f;
                if ((unsigned)ry < 19u && (unsigned)rx < 27u) {
                    const char* base = smem + TILE_OFF + (ry * 28 + rx) * 16;
                    uint4 c00 = *(const uint4*)(base);
                    uint4 c01 = *(const uint4*)(base + 16);
                    uint4 c10 = *(const uint4*)(base + 448);
                    uint4 c11 = *(const uint4*)(base + 464);
                    const __half2* h00 = (const __half2*)&c00;
                    const __half2* h01 = (const __half2*)&c01;
                    const __half2* h10 = (const __half2*)&c10;
                    const __half2* h11 = (const __half2*)&c11;
                    #pragma unroll
                    for (int j = 0; j < 4; j++) {
                        float2 f00 = __half22float2(h00[j]);
                        float2 f01 = __half22float2(h01[j]);
                        float2 f10 = __half22float2(h10[j]);
                        float2 f11 = __half22float2(h11[j]);
                        a8[2*j]   = tw0[t]*f00.x + tw1[t]*f01.x + tw2[t]*f10.x + tw3[t]*f11.x;
                        a8[2*j+1] = tw0[t]*f00.y + tw1[t]*f01.y + tw2[t]*f10.y + tw3[t]*f11.y;
                    }
                } else {
                    // rare fallback: gmem gather with explicit validity
                    int iy0 = tiy[t], ix0 = tix[t];
                    float ws[4] = {tw0[t], tw1[t], tw2[t], tw3[t]};
                    int cy[4] = {iy0, iy0, iy0 + 1, iy0 + 1};
                    int cx[4] = {ix0, ix0 + 1, ix0, ix0 + 1};
                    #pragma unroll
                    for (int q = 0; q < 4; q++) {
                        if ((unsigned)cy[q] < 256u && (unsigned)cx[q] < 256u) {
                            const uint4 v = *(const uint4*)(ftb + (((size_t)((cy[q] << 8) + cx[q])) << 7) + cbase);
                            const __half2* hv = (const __half2*)&v;
                            #pragma unroll
                            for (int j = 0; j < 4; j++) {
                                float2 f = __half22float2(hv[j]);
                                a8[2*j]   += ws[q] * f.x;
                                a8[2*j+1] += ws[q] * f.y;
                            }
                        }
                    }
                }
                __half2 o2[4];
                #pragma unroll
                for (int j = 0; j < 4; j++) o2[j] = __floats2half2_rn(a8[2*j], a8[2*j+1]);
                *(uint4*)(smem + S_OFF + px * 176 + k * 16) = *(uint4*)o2;
            }
        }
        __syncthreads();

        // ---- HMMA: acc[32px x 32oc per warp] += S x Wh (K=80) ----
        #pragma unroll
        for (int ks = 0; ks < 5; ks++) {
            uint32_t A[2][4];
            #pragma unroll
            for (int mt = 0; mt < 2; mt++) {
                uint32_t addr = sb + S_OFF +
                    (uint32_t)((wm * 32 + mt * 16 + lrow) * 176 + ks * 32 + lcol * 16);
                LDMATRIX_X4(A[mt][0], A[mt][1], A[mt][2], A[mt][3], addr);
            }
            #pragma unroll
            for (int nt = 0; nt < 4; nt++) {
                uint32_t baddr = sb + WH_OFF +
                    (uint32_t)((wn * 32 + nt * 8 + i4) * 176 + ks * 32 + k4 * 4);
                uint32_t b0, b1;
                asm volatile("ld.shared.b32 %0, [%1];" : "=r"(b0) : "r"(baddr));
                asm volatile("ld.shared.b32 %0, [%1];" : "=r"(b1) : "r"(baddr + 16));
                #pragma unroll
                for (int mt = 0; mt < 2; mt++) {
                    MMA16816(acc[mt][nt][0], acc[mt][nt][1], acc[mt][nt][2], acc[mt][nt][3],
                             A[mt][0], A[mt][1], A[mt][2], A[mt][3], b0, b1);
                }
            }
        }
    }

    // ---- epilogue: stage D to smem [64 oc][128 px], then coalesced stores ----
    __syncthreads();
    float* E = (float*)smem;
    #pragma unroll
    for (int mt = 0; mt < 2; mt++) {
        #pragma unroll
        for (int nt = 0; nt < 4; nt++) {
            #pragma unroll
            for (int q = 0; q < 4; q++) {
                int px = wm * 32 + mt * 16 + (lane >> 2) + ((q >> 1) << 3);
                int oc = wn * 32 + nt * 8 + ((lane & 3) << 1) + (q & 1);
                E[oc * 128 + px] = acc[mt][nt][q];
            }
        }
    }
    __syncthreads();
    #pragma unroll
    for (int j = 0; j < 8; j++) {
        int lin = tid + (j << 8);        // 0..2047
        int oc = lin >> 5;
        int u  = lin & 31;
        int px0 = u << 2;
        int pr = px0 >> 4, pc = px0 & 15;
        float bi = __ldg(bias + oc);
        float4 v = *(float4*)(E + oc * 128 + px0);
        v.x += bi; v.y += bi; v.z += bi; v.w += bi;
        *(float4*)(out + ((b * 64 + oc) << 16) + ((ty + pr) << 8) + tx + pc) = v;
    }
}

// ---------------------------------------------------------------------------
// Launch
// ---------------------------------------------------------------------------
extern "C" void kernel_launch(void* const* d_in, const int* in_sizes, int n_in,
                              void* d_out, int out_size)
{
    const float* ref    = (const float*)d_in[0];
    const float* nbr    = (const float*)d_in[1];
    const float* off_w  = (const float*)d_in[2];
    const float* off_b  = (const float*)d_in[3];
    const float* mask_w = (const float*)d_in[4];
    const float* mask_b = (const float*)d_in[5];
    const float* weight = (const float*)d_in[6];
    const float* bias   = (const float*)d_in[7];
    float* out = (float*)d_out;

    // Stage T: channel-last fp16 transpose of concat(ref, nbr)
    {
        dim3 grid(WW / 32, HH, BB);
        transpose_kernel<<<grid, 256>>>(ref, nbr);
    }
    // Stage 0: weight prepacks
    prepack_w_kernel<<<(8 * 9 * 224 * 16 + 255) / 256, 256>>>(off_w, mask_w);
    prepack_we_kernel<<<(8 * 64 * 88 + 255) / 256, 256>>>(weight);

    // Stage 1: conv -> offsets + sigmoid(mask)
    {
        cudaFuncSetAttribute(conv_mma_kernel,
                             cudaFuncAttributeMaxDynamicSharedMemorySize, SMEM_TOT);
        dim3 grid(WW / 16, HH / 8, BB);
        conv_mma_kernel<<<grid, 256, SMEM_TOT>>>(off_b, mask_b);
    }
    // Stage 2: smem-tile sampling + HMMA einsum + bias
    {
        cudaFuncSetAttribute(samp_einsum_kernel,
                             cudaFuncAttributeMaxDynamicSharedMemorySize, SMEM_SAMP);
        dim3 grid(WW / 16, HH / 8, BB);
        samp_einsum_kernel<<<grid, 256, SMEM_SAMP>>>(bias, out);
    }
}

// round 7
// speedup vs baseline: 7.4093x; 1.0455x over previous
#include <cuda_runtime.h>
#include <cuda_fp16.h>
#include <math.h>
#include <stdint.h>

// ---------------------------------------------------------------------------
// Problem constants
// ---------------------------------------------------------------------------
#define BB   2
#define CC   64
#define HH   256
#define WW   256
#define DG   8
#define CG   8
#define NOFF 144
#define NMSK 72
#define NOM  216
#define HW   65536

// scratch
__device__ float  g_offmask[(size_t)BB * NOM * HW];   // conv output (fp32 planes)
__device__ __half g_featT[(size_t)BB * HW * 128];     // [b][y][x][128c] fp16
__device__ uint4  g_wconv[32256];                     // conv W: [chunk8][half2][tap9][oc112][ci16] f16
__device__ uint4  g_weinsum[5632];                    // einsum W: [g8][oc64][ck88] f16

// warp-level HMMA
#define MMA16816(d0,d1,d2,d3,a0,a1,a2,a3,b0,b1) \
    asm volatile("mma.sync.aligned.m16n8k16.row.col.f32.f16.f16.f32 " \
        "{%0,%1,%2,%3}, {%4,%5,%6,%7}, {%8,%9}, {%0,%1,%2,%3};" \
        : "+f"(d0), "+f"(d1), "+f"(d2), "+f"(d3) \
        : "r"(a0), "r"(a1), "r"(a2), "r"(a3), "r"(b0), "r"(b1))

#define LDMATRIX_X4(r0,r1,r2,r3,addr) \
    asm volatile("ldmatrix.sync.aligned.m8n8.x4.shared.b16 {%0,%1,%2,%3}, [%4];" \
        : "=r"(r0), "=r"(r1), "=r"(r2), "=r"(r3) : "r"(addr))

#define CP_ASYNC16(dst, src) \
    asm volatile("cp.async.cg.shared.global [%0], [%1], 16;" :: "r"(dst), "l"(src))
#define CP_ASYNC16Z(dst, src, sz) \
    asm volatile("cp.async.cg.shared.global [%0], [%1], 16, %2;" :: "r"(dst), "l"(src), "r"(sz))
#define CP_COMMIT()  asm volatile("cp.async.commit_group;" ::: "memory")
#define CP_WAIT_ALL() asm volatile("cp.async.wait_group 0;" ::: "memory")
#define CP_WAIT_1()  asm volatile("cp.async.wait_group 1;" ::: "memory")

static __device__ __forceinline__ uint32_t smem_u32(const void* p) {
    uint32_t a;
    asm("{ .reg .u64 t; cvta.to.shared.u64 t, %1; cvt.u32.u64 %0, t; }" : "=r"(a) : "l"(p));
    return a;
}

// ---------------------------------------------------------------------------
// Kernel T: transpose concat(ref, nbr) to channel-last fp16 [b][y][x][128]
// ---------------------------------------------------------------------------
__global__ __launch_bounds__(256, 4)
void transpose_kernel(const float* __restrict__ ref, const float* __restrict__ nbr)
{
    __shared__ float t[128][33];
    const int b  = blockIdx.z;
    const int y  = blockIdx.y;
    const int x0 = blockIdx.x << 5;
    const int tid = threadIdx.x;

    #pragma unroll
    for (int i = 0; i < 16; i++) {
        int idx = tid + (i << 8);
        int c = idx >> 5;
        int x = idx & 31;
        const float* src = (c < 64) ? ref : nbr;
        t[c][x] = __ldg(src + (((size_t)b * 64 + (c & 63)) << 16) + (y << 8) + x0 + x);
    }
    __syncthreads();
    __half* dst = g_featT + ((((size_t)b << 16) + (y << 8) + x0) << 7);
    #pragma unroll
    for (int i = 0; i < 8; i++) {
        int idx = tid + (i << 8);
        int x  = idx >> 6;
        int c2 = idx & 63;
        __half2 h = __floats2half2_rn(t[2 * c2][x], t[2 * c2 + 1][x]);
        *(__half2*)(dst + (size_t)x * 128 + 2 * c2) = h;
    }
}

// ---------------------------------------------------------------------------
// Kernel 0a: prepack conv weights fp16 [chunk8][half2][tap9][oc112][ci16]
// ---------------------------------------------------------------------------
__global__ void prepack_w_kernel(const float* __restrict__ off_w,
                                 const float* __restrict__ mask_w)
{
    int idx = blockIdx.x * 256 + threadIdx.x;
    if (idx >= 8 * 2 * 9 * 112 * 16) return;
    int cl = idx & 15;
    int r  = idx >> 4;
    int ocl = r % 112;
    int r2  = r / 112;
    int t   = r2 % 9;
    int r3  = r2 / 9;
    int h   = r3 & 1;
    int c   = r3 >> 1;
    int oc  = h * 112 + ocl;
    int ci  = c * 16 + cl;
    float v = 0.f;
    if (oc < NOFF)      v = off_w[(oc * 128 + ci) * 9 + t];
    else if (oc < NOM)  v = mask_w[((oc - NOFF) * 128 + ci) * 9 + t];
    ((__half*)g_wconv)[idx] = __float2half_rn(v);
}

// ---------------------------------------------------------------------------
// Kernel 0b: prepack einsum weights fp16 [g][oc 64][ck2 88], ck2 = k*8+c
// ---------------------------------------------------------------------------
__global__ void prepack_we_kernel(const float* __restrict__ weight)
{
    int idx = blockIdx.x * 256 + threadIdx.x;
    if (idx >= 8 * 64 * 88) return;
    int ck2 = idx % 88;
    int r   = idx / 88;
    int oc  = r & 63;
    int g   = r >> 6;
    float v = 0.f;
    if (ck2 < 72) {
        int k = ck2 >> 3;
        int c = ck2 & 7;
        v = weight[(oc * 64 + g * 8 + c) * 9 + k];
    }
    ((__half*)g_weinsum)[idx] = __float2half_rn(v);
}

// ---------------------------------------------------------------------------
// Kernel 1: 3x3 conv as 9 shifted 1x1 HMMA GEMMs.
// Block: 8x16 px tile x 112 oc (half the channels). 256 threads, occ 2.
// Warp: wm = wid&3 (32 px = 2 image rows), wn = wid>>2 (56 oc = 7 n-tiles).
// patch: 10x18 px x 16 ci f16, 48 B px stride, double-buffered;
// weights: [tap9][oc112][ci16] f16 per chunk, double-buffered (contiguous copy).
// ---------------------------------------------------------------------------
#define PATCH_SZ  8704
#define WOFF      17408
#define WSZ       32256           // 9*112*32
#define BIAS_OFF  81920           // WOFF + 2*WSZ
#define SMEM_TOT  82944

__global__ __launch_bounds__(256, 2)
void conv_mma_kernel(const float* __restrict__ off_b,
                     const float* __restrict__ mask_b)
{
    extern __shared__ char smem[];
    const uint32_t sb = smem_u32(smem);
    const int tid  = threadIdx.x;
    const int wid  = tid >> 5;
    const int lane = tid & 31;
    const int bz   = blockIdx.z;
    const int b    = bz >> 1;
    const int half = bz & 1;
    const int ocbase = half * 112;
    const int ty = blockIdx.y << 3;
    const int tx = blockIdx.x << 4;
    const int wm = wid & 3;       // 32-px group (2 image rows)
    const int wn = wid >> 2;      // 56-oc group

    float* bias_s = (float*)(smem + BIAS_OFF);
    if (tid < 112) {
        int oc = ocbase + tid;
        float bi = 0.f;
        if (oc < NOFF)     bi = off_b[oc];
        else if (oc < NOM) bi = mask_b[oc - NOFF];
        bias_s[tid] = bi;
    }

    const __half* ftb = g_featT + (((size_t)b << 16) << 7);

    // patch tasks: 360 = 180 px x 2 halves; task0 = tid, task1 = tid+256 (tid<104)
    int pl0 = tid % 180, h0 = tid / 180;
    int t1v = (tid < 104);
    int pl1 = (tid + 256) % 180, h1 = (tid + 256) / 180;
    int py0 = pl0 / 18, px0 = pl0 - py0 * 18;
    int py1 = pl1 / 18, px1 = pl1 - py1 * 18;
    int gy0 = ty - 1 + py0, gx0 = tx - 1 + px0;
    int gy1 = ty - 1 + py1, gx1 = tx - 1 + px1;
    bool v0 = ((unsigned)gy0 < 256u) && ((unsigned)gx0 < 256u);
    bool v1 = t1v && ((unsigned)gy1 < 256u) && ((unsigned)gx1 < 256u);
    const __half* src0 = ftb + (((size_t)(v0 ? ((gy0 << 8) + gx0) : 0)) << 7) + h0 * 8;
    const __half* src1 = ftb + (((size_t)(v1 ? ((gy1 << 8) + gx1) : 0)) << 7) + h1 * 8;
    const uint32_t d0 = (uint32_t)(pl0 * 48 + h0 * 16);
    const uint32_t d1 = (uint32_t)(pl1 * 48 + h1 * 16);
    const uint32_t z0 = v0 ? 16u : 0u;
    const uint32_t z1 = v1 ? 16u : 0u;

    float acc[2][7][4];
    #pragma unroll
    for (int mt = 0; mt < 2; mt++)
        #pragma unroll
        for (int nt = 0; nt < 7; nt++)
            #pragma unroll
            for (int q = 0; q < 4; q++) acc[mt][nt][q] = 0.f;

    const int i4 = lane >> 2;
    const int k4 = lane & 3;
    const int lrow = lane & 15;
    const int lcol = lane >> 4;

    // prologue: issue chunk 0 (weights + patch)
    {
        const uint4* wsrc = g_wconv + half * 2016;
        uint32_t wdst = sb + WOFF;
        #pragma unroll
        for (int i = 0; i < 8; i++) {
            int idx = tid + (i << 8);
            if (idx < 2016) CP_ASYNC16(wdst + idx * 16, (const void*)(wsrc + idx));
        }
        CP_ASYNC16Z(sb + d0, (const void*)src0, z0);
        if (t1v) CP_ASYNC16Z(sb + d1, (const void*)src1, z1);
        CP_COMMIT();
    }

    for (int c = 0; c < 8; c++) {
        const int s = c & 1;
        __syncthreads();
        if (c < 7) {
            const uint4* wsrc = g_wconv + (c + 1) * 4032 + half * 2016;
            uint32_t wdst = sb + WOFF + (s ^ 1) * WSZ;
            #pragma unroll
            for (int i = 0; i < 8; i++) {
                int idx = tid + (i << 8);
                if (idx < 2016) CP_ASYNC16(wdst + idx * 16, (const void*)(wsrc + idx));
            }
            int cb = (c + 1) * 16;
            CP_ASYNC16Z(sb + (s ^ 1) * PATCH_SZ + d0, (const void*)(src0 + cb), z0);
            if (t1v) CP_ASYNC16Z(sb + (s ^ 1) * PATCH_SZ + d1, (const void*)(src1 + cb), z1);
            CP_COMMIT();
            CP_WAIT_1();
        } else {
            CP_WAIT_ALL();
        }
        __syncthreads();
        // ---- MMA chunk c ----
        const uint32_t patch_s = sb + s * PATCH_SZ;
        const uint32_t wbuf = sb + WOFF + s * WSZ;
        #pragma unroll 1
        for (int t = 0; t < 9; t++) {
            const int dy = t / 3;
            const int dx = t - dy * 3;
            uint32_t A[2][4];
            #pragma unroll
            for (int mt = 0; mt < 2; mt++) {
                int py = wm * 2 + mt + dy;          // patch row (0..9)
                uint32_t addr = patch_s + (uint32_t)((py * 18 + dx + lrow) * 48 + lcol * 16);
                LDMATRIX_X4(A[mt][0], A[mt][1], A[mt][2], A[mt][3], addr);
            }
            const uint32_t bbase = wbuf + (uint32_t)(t * 3584 + wn * 1792 + i4 * 32 + k4 * 4);
            #pragma unroll
            for (int nt = 0; nt < 7; nt++) {
                uint32_t b0, b1;
                asm volatile("ld.shared.b32 %0, [%1];" : "=r"(b0) : "r"(bbase + nt * 256));
                asm volatile("ld.shared.b32 %0, [%1];" : "=r"(b1) : "r"(bbase + nt * 256 + 16));
                #pragma unroll
                for (int mt = 0; mt < 2; mt++) {
                    MMA16816(acc[mt][nt][0], acc[mt][nt][1], acc[mt][nt][2], acc[mt][nt][3],
                             A[mt][0], A[mt][1], A[mt][2], A[mt][3], b0, b1);
                }
            }
        }
    }

    // ---- epilogue ----
    __syncthreads();
    float* omb = g_offmask + (size_t)b * NOM * HW;
    #pragma unroll
    for (int mt = 0; mt < 2; mt++) {
        #pragma unroll
        for (int nt = 0; nt < 7; nt++) {
            int ocl0 = wn * 56 + nt * 8 + (lane & 3) * 2;
            #pragma unroll
            for (int q = 0; q < 4; q++) {
                int ocl = ocl0 + (q & 1);
                int oc  = ocbase + ocl;
                if (oc >= NOM) continue;
                int px = wm * 32 + mt * 16 + (lane >> 2) + ((q >> 1) << 3);
                int y = ty + (px >> 4);
                int x = tx + (px & 15);
                float val = acc[mt][nt][q] + bias_s[ocl];
                if (oc >= NOFF) val = 1.f / (1.f + __expf(-val));
                omb[(size_t)oc * HW + (y << 8) + x] = val;
            }
        }
    }
}

// ---------------------------------------------------------------------------
// Kernel 2: deformable sampling from smem halo tile + HMMA einsum.
// ---------------------------------------------------------------------------
#define S_OFF     0
#define TILE_OFF  22528
#define WH_OFF    31488
#define SMEM_SAMP 42752

__global__ __launch_bounds__(256, 2)
void samp_einsum_kernel(const float* __restrict__ bias,
                        float* __restrict__ out)
{
    extern __shared__ char smem[];
    const uint32_t sb = smem_u32(smem);
    const int b   = blockIdx.z;
    const int ty  = blockIdx.y << 3;
    const int tx  = blockIdx.x << 4;
    const int tid = threadIdx.x;
    const int wid  = tid >> 5;
    const int lane = tid & 31;
    const int wm = wid & 3;
    const int wn = wid >> 2;
    const int i4 = lane >> 2;
    const int k4 = lane & 3;
    const int lrow = lane & 15;
    const int lcol = lane >> 4;

    const float*  om  = g_offmask + (size_t)b * NOM * HW;
    const __half* ftb = g_featT + (((size_t)b << 16) << 7);

    if (tid < 128) {
        uint4 z = make_uint4(0, 0, 0, 0);
        *(uint4*)(smem + S_OFF + tid * 176 + 144) = z;
        *(uint4*)(smem + S_OFF + tid * 176 + 160) = z;
    }

    float acc[2][4][4];
    #pragma unroll
    for (int mt = 0; mt < 2; mt++)
        #pragma unroll
        for (int nt = 0; nt < 4; nt++)
            #pragma unroll
            for (int q = 0; q < 4; q++) acc[mt][nt][q] = 0.f;

    for (int g = 0; g < 8; g++) {
        const int cbase = 64 + g * 8;
        __syncthreads();
        #pragma unroll
        for (int jj = 0; jj < 3; jj++) {
            int j = tid + jj * 256;
            if (j < 560) {
                int r  = j / 28;
                int cc = j - r * 28;
                int gy = ty - 6 + r;
                int gx = tx - 6 + cc;
                bool pv = ((unsigned)gy < 256u) && ((unsigned)gx < 256u);
                const __half* src = ftb + (((size_t)(pv ? ((gy << 8) + gx) : 0)) << 7) + cbase;
                CP_ASYNC16Z(sb + TILE_OFF + j * 16, (const void*)src, pv ? 16u : 0u);
            }
        }
        #pragma unroll
        for (int jj = 0; jj < 3; jj++) {
            int j = tid + jj * 256;
            if (j < 704) CP_ASYNC16(sb + WH_OFF + j * 16, (const void*)(g_weinsum + g * 704 + j));
        }
        CP_COMMIT();

        float tw0[5], tw1[5], tw2[5], tw3[5];
        int tiy[5], tix[5];
        #pragma unroll
        for (int t = 0; t < 5; t++) {
            int i = tid + t * 256;
            if (i < 1152) {
                int px = i & 127;
                int k  = i >> 7;
                int pr = px >> 4, pc = px & 15;
                int y = ty + pr, x = tx + pc;
                int pix = (y << 8) + x;
                int ch  = g * 9 + k;
                float dy = om[(ch * 2) * HW + pix];
                float dx = om[(ch * 2 + 1) * HW + pix];
                float m  = om[(NOFF + ch) * HW + pix];
                float sy = (float)(y - 1 + k / 3) + dy;
                float sx = (float)(x - 1 + (k - (k / 3) * 3)) + dx;
                float y0f = floorf(sy), x0f = floorf(sx);
                float wy = sy - y0f, wx = sx - x0f;
                tiy[t] = (int)y0f;
                tix[t] = (int)x0f;
                tw0[t] = (1.f - wy) * (1.f - wx) * m;
                tw1[t] = (1.f - wy) * wx * m;
                tw2[t] = wy * (1.f - wx) * m;
                tw3[t] = wy * wx * m;
            }
        }
        CP_WAIT_ALL();
        __syncthreads();

        #pragma unroll
        for (int t = 0; t < 5; t++) {
            int i = tid + t * 256;
            if (i < 1152) {
                int px = i & 127;
                int k  = i >> 7;
                int ry = tiy[t] - (ty - 6);
                int rx = tix[t] - (tx - 6);
                float a8[8];
                #pragma unroll
                for (int cc = 0; cc < 8; cc++) a8[cc] = 0.f;
                if ((unsigned)ry < 19u && (unsigned)rx < 27u) {
                    const char* base = smem + TILE_OFF + (ry * 28 + rx) * 16;
                    uint4 c00 = *(const uint4*)(base);
                    uint4 c01 = *(const uint4*)(base + 16);
                    uint4 c10 = *(const uint4*)(base + 448);
                    uint4 c11 = *(const uint4*)(base + 464);
                    const __half2* h00 = (const __half2*)&c00;
                    const __half2* h01 = (const __half2*)&c01;
                    const __half2* h10 = (const __half2*)&c10;
                    const __half2* h11 = (const __half2*)&c11;
                    #pragma unroll
                    for (int j = 0; j < 4; j++) {
                        float2 f00 = __half22float2(h00[j]);
                        float2 f01 = __half22float2(h01[j]);
                        float2 f10 = __half22float2(h10[j]);
                        float2 f11 = __half22float2(h11[j]);
                        a8[2*j]   = tw0[t]*f00.x + tw1[t]*f01.x + tw2[t]*f10.x + tw3[t]*f11.x;
                        a8[2*j+1] = tw0[t]*f00.y + tw1[t]*f01.y + tw2[t]*f10.y + tw3[t]*f11.y;
                    }
                } else {
                    int iy0 = tiy[t], ix0 = tix[t];
                    float ws[4] = {tw0[t], tw1[t], tw2[t], tw3[t]};
                    int cy[4] = {iy0, iy0, iy0 + 1, iy0 + 1};
                    int cx[4] = {ix0, ix0 + 1, ix0, ix0 + 1};
                    #pragma unroll
                    for (int q = 0; q < 4; q++) {
                        if ((unsigned)cy[q] < 256u && (unsigned)cx[q] < 256u) {
                            const uint4 v = *(const uint4*)(ftb + (((size_t)((cy[q] << 8) + cx[q])) << 7) + cbase);
                            const __half2* hv = (const __half2*)&v;
                            #pragma unroll
                            for (int j = 0; j < 4; j++) {
                                float2 f = __half22float2(hv[j]);
                                a8[2*j]   += ws[q] * f.x;
                                a8[2*j+1] += ws[q] * f.y;
                            }
                        }
                    }
                }
                __half2 o2[4];
                #pragma unroll
                for (int j = 0; j < 4; j++) o2[j] = __floats2half2_rn(a8[2*j], a8[2*j+1]);
                *(uint4*)(smem + S_OFF + px * 176 + k * 16) = *(uint4*)o2;
            }
        }
        __syncthreads();

        #pragma unroll
        for (int ks = 0; ks < 5; ks++) {
            uint32_t A[2][4];
            #pragma unroll
            for (int mt = 0; mt < 2; mt++) {
                uint32_t addr = sb + S_OFF +
                    (uint32_t)((wm * 32 + mt * 16 + lrow) * 176 + ks * 32 + lcol * 16);
                LDMATRIX_X4(A[mt][0], A[mt][1], A[mt][2], A[mt][3], addr);
            }
            #pragma unroll
            for (int nt = 0; nt < 4; nt++) {
                uint32_t baddr = sb + WH_OFF +
                    (uint32_t)((wn * 32 + nt * 8 + i4) * 176 + ks * 32 + k4 * 4);
                uint32_t b0, b1;
                asm volatile("ld.shared.b32 %0, [%1];" : "=r"(b0) : "r"(baddr));
                asm volatile("ld.shared.b32 %0, [%1];" : "=r"(b1) : "r"(baddr + 16));
                #pragma unroll
                for (int mt = 0; mt < 2; mt++) {
                    MMA16816(acc[mt][nt][0], acc[mt][nt][1], acc[mt][nt][2], acc[mt][nt][3],
                             A[mt][0], A[mt][1], A[mt][2], A[mt][3], b0, b1);
                }
            }
        }
    }

    __syncthreads();
    float* E = (float*)smem;
    #pragma unroll
    for (int mt = 0; mt < 2; mt++) {
        #pragma unroll
        for (int nt = 0; nt < 4; nt++) {
            #pragma unroll
            for (int q = 0; q < 4; q++) {
                int px = wm * 32 + mt * 16 + (lane >> 2) + ((q >> 1) << 3);
                int oc = wn * 32 + nt * 8 + ((lane & 3) << 1) + (q & 1);
                E[oc * 128 + px] = acc[mt][nt][q];
            }
        }
    }
    __syncthreads();
    #pragma unroll
    for (int j = 0; j < 8; j++) {
        int lin = tid + (j << 8);
        int oc = lin >> 5;
        int u  = lin & 31;
        int px0 = u << 2;
        int pr = px0 >> 4, pc = px0 & 15;
        float bi = __ldg(bias + oc);
        float4 v = *(float4*)(E + oc * 128 + px0);
        v.x += bi; v.y += bi; v.z += bi; v.w += bi;
        *(float4*)(out + ((b * 64 + oc) << 16) + ((ty + pr) << 8) + tx + pc) = v;
    }
}

// ---------------------------------------------------------------------------
// Launch
// ---------------------------------------------------------------------------
extern "C" void kernel_launch(void* const* d_in, const int* in_sizes, int n_in,
                              void* d_out, int out_size)
{
    const float* ref    = (const float*)d_in[0];
    const float* nbr    = (const float*)d_in[1];
    const float* off_w  = (const float*)d_in[2];
    const float* off_b  = (const float*)d_in[3];
    const float* mask_w = (const float*)d_in[4];
    const float* mask_b = (const float*)d_in[5];
    const float* weight = (const float*)d_in[6];
    const float* bias   = (const float*)d_in[7];
    float* out = (float*)d_out;

    {
        dim3 grid(WW / 32, HH, BB);
        transpose_kernel<<<grid, 256>>>(ref, nbr);
    }
    prepack_w_kernel<<<(8 * 2 * 9 * 112 * 16 + 255) / 256, 256>>>(off_w, mask_w);
    prepack_we_kernel<<<(8 * 64 * 88 + 255) / 256, 256>>>(weight);

    {
        cudaFuncSetAttribute(conv_mma_kernel,
                             cudaFuncAttributeMaxDynamicSharedMemorySize, SMEM_TOT);
        dim3 grid(WW / 16, HH / 8, BB * 2);   // z = b*2 + oc-half
        conv_mma_kernel<<<grid, 256, SMEM_TOT>>>(off_b, mask_b);
    }
    {
        cudaFuncSetAttribute(samp_einsum_kernel,
                             cudaFuncAttributeMaxDynamicSharedMemorySize, SMEM_SAMP);
        dim3 grid(WW / 16, HH / 8, BB);
        samp_einsum_kernel<<<grid, 256, SMEM_SAMP>>>(bias, out);
    }
}